// round 1
// baseline (speedup 1.0000x reference)
#include <cuda_runtime.h>
#include <cstdint>

// Problem constants
#define IMG_N     2048
#define OW        2044          // 2048 - 5 + 1
#define OH        2044
#define DOUT      14            // 16 - 3 + 1
#define NBITS     16

// Tiling
#define TW        128           // output cols per CTA
#define TH        8             // output rows per CTA
#define IC        (TW + 4)      // input cols needed  (132)
#define ICP       136           // padded col stride (floats)
#define IR        (TH + 4)      // input rows needed  (12)
#define NTHREADS  256

// smem: bit-plane floats [IR][NBITS][ICP] + duplicated weight pairs
#define SDATA_FLOATS (IR * NBITS * ICP)
#define SMEM_BYTES   (SDATA_FLOATS * 4 + 75 * 8 + 16)

typedef unsigned long long ull;

__device__ __forceinline__ void fma2(ull& acc, ull a, ull b) {
    asm("fma.rn.f32x2 %0, %1, %2, %0;" : "+l"(acc) : "l"(a), "l"(b));
}

__global__ void __launch_bounds__(NTHREADS, 2)
conv2dto3d_kernel(const int* __restrict__ x,
                  const float* __restrict__ weight,
                  const float* __restrict__ bias,
                  float* __restrict__ out)
{
    extern __shared__ unsigned char smem_raw[];
    float* sdata = reinterpret_cast<float*>(smem_raw);                 // [IR][NBITS][ICP]
    ull*   wpair = reinterpret_cast<ull*>(smem_raw + SDATA_FLOATS * 4); // 75 packed {w,w}

    const int tid   = threadIdx.x;
    const int wbase = blockIdx.x * TW;
    const int hbase = blockIdx.y * TH;

    // duplicate weights into {w,w} pairs
    if (tid < 75) {
        float w = weight[tid];
        float2 p = make_float2(w, w);
        wpair[tid] = *reinterpret_cast<ull*>(&p);
    }

    // ---- Phase 1: expand tile to fp32 bit-planes in smem ----
    // sdata[rr][k][cc] = bit k of x[hbase+rr][wbase+cc] as 0.0f/1.0f
    for (int p = tid; p < IR * IC; p += NTHREADS) {
        int rr = p / IC;
        int cc = p - rr * IC;
        int ri = hbase + rr; if (ri > IMG_N - 1) ri = IMG_N - 1;   // clamp (only feeds invalid outputs)
        int ci = wbase + cc; if (ci > IMG_N - 1) ci = IMG_N - 1;
        unsigned v = (unsigned)x[ri * IMG_N + ci];
        float* dst = sdata + (rr * NBITS) * ICP + cc;
        #pragma unroll
        for (int k = 0; k < NBITS; k++) {
            unsigned bit = (v >> k) & 1u;
            dst[k * ICP] = __uint_as_float(bit * 0x3F800000u);
        }
    }
    __syncthreads();

    // ---- Phase 2: each thread computes 4 output columns x 14 depths ----
    const int wg   = tid & 31;        // column group (4 cols each -> 128)
    const int r    = tid >> 5;        // local output row 0..7
    const int col0 = wg * 4;

    ull accA[DOUT];   // output cols (col0, col0+1)
    ull accB[DOUT];   // output cols (col0+2, col0+3)
    #pragma unroll
    for (int z = 0; z < DOUT; z++) { accA[z] = 0ull; accB[z] = 0ull; }

    #pragma unroll
    for (int i = 0; i < 5; i++) {
        // weight pairs for this kernel row: wv[d*5+j] = {w[d,i,j], w[d,i,j]}
        ull wv[15];
        #pragma unroll
        for (int d = 0; d < 3; d++)
            #pragma unroll
            for (int j = 0; j < 5; j++)
                wv[d * 5 + j] = wpair[d * 25 + i * 5 + j];

        const float* rowp = sdata + ((r + i) * NBITS) * ICP + col0;

        #pragma unroll
        for (int k = 0; k < NBITS; k++) {
            const float* pk = rowp + k * ICP;
            // aligned packed pairs of adjacent columns
            ull p0 = *reinterpret_cast<const ull*>(pk + 0);   // cols (0,1)
            ull p1 = *reinterpret_cast<const ull*>(pk + 2);   // cols (2,3)
            ull p2 = *reinterpret_cast<const ull*>(pk + 4);   // cols (4,5)
            ull p3 = *reinterpret_cast<const ull*>(pk + 6);   // cols (6,7)
            // odd-offset pairs via register merge
            ull q0 = (p0 >> 32) | (p1 << 32);                 // cols (1,2)
            ull q1 = (p1 >> 32) | (p2 << 32);                 // cols (3,4)
            ull q2 = (p2 >> 32) | (p3 << 32);                 // cols (5,6)
            ull P[7] = { p0, q0, p1, q1, p2, q2, p3 };        // pair starting at local col base 0..6

            #pragma unroll
            for (int d = 0; d < 3; d++) {
                const int z = k - d;
                if (z >= 0 && z < DOUT) {
                    #pragma unroll
                    for (int j = 0; j < 5; j++) {
                        fma2(accA[z], wv[d * 5 + j], P[j]);       // outputs (col0,   col0+1)
                        fma2(accB[z], wv[d * 5 + j], P[j + 2]);   // outputs (col0+2, col0+3)
                    }
                }
            }
        }
    }

    // ---- Phase 3: store ----
    const int h = hbase + r;
    const int w = wbase + col0;
    if (h < OH && w < OW) {
        const float b = bias[0];
        const bool full = (w + 4 <= OW);
        #pragma unroll
        for (int z = 0; z < DOUT; z++) {
            float2 a  = *reinterpret_cast<float2*>(&accA[z]);
            float2 bb = *reinterpret_cast<float2*>(&accB[z]);
            long off = ((long)z * OH + h) * OW + w;
            if (full) {
                float4 v = make_float4(a.x + b, a.y + b, bb.x + b, bb.y + b);
                *reinterpret_cast<float4*>(out + off) = v;
            } else {
                float vals[4] = { a.x + b, a.y + b, bb.x + b, bb.y + b };
                #pragma unroll
                for (int c = 0; c < 4; c++)
                    if (w + c < OW) out[off + c] = vals[c];
            }
        }
    }
}

extern "C" void kernel_launch(void* const* d_in, const int* in_sizes, int n_in,
                              void* d_out, int out_size)
{
    const int*   x      = (const int*)d_in[0];
    const float* weight = (const float*)d_in[1];
    const float* bias   = (const float*)d_in[2];
    float*       out    = (float*)d_out;

    cudaFuncSetAttribute(conv2dto3d_kernel,
                         cudaFuncAttributeMaxDynamicSharedMemorySize, SMEM_BYTES);

    dim3 grid((OW + TW - 1) / TW, (OH + TH - 1) / TH);   // 16 x 256
    conv2dto3d_kernel<<<grid, NTHREADS, SMEM_BYTES>>>(x, weight, bias, out);
}

// round 3
// speedup vs baseline: 1.2298x; 1.2298x over previous
#include <cuda_runtime.h>
#include <cstdint>

#define IMG_N  2048
#define OW     2044
#define OH     2044
#define TW     128
#define TH     8
#define IR     12          // TH + 4 input rows
#define IC     132         // TW + 4 input cols
#define ICP    136         // padded col stride (bf16 elements)
#define NTH    256

#define PLANES_U16 (IR * 16 * ICP)           // 26112 bf16
#define WOFF       (PLANES_U16 * 2)          // 52224 bytes
#define SMEM_BYTES (WOFF + 75 * 8)           // + 75 packed weight pairs

typedef unsigned long long ull;
typedef unsigned int u32;

__device__ __forceinline__ void fma2(ull& acc, ull a, ull b) {
    asm("fma.rn.f32x2 %0, %1, %2, %0;" : "+l"(acc) : "l"(a), "l"(b));
}
__device__ __forceinline__ ull pack2(u32 lo, u32 hi) {
    ull r; asm("mov.b64 %0, {%1, %2};" : "=l"(r) : "r"(lo), "r"(hi)); return r;
}

// One z-pass: outputs z in [ZLO, ZLO+6], consuming bit planes k in [ZLO, ZLO+8].
template<int ZLO>
__device__ __forceinline__ void run_pass(const uint16_t* __restrict__ sp,
                                         const ull* __restrict__ wps,
                                         int r, int col0, ull* accA, ull* accB)
{
    #pragma unroll
    for (int z = 0; z < 7; z++) { accA[z] = 0ull; accB[z] = 0ull; }

    #pragma unroll 1
    for (int i = 0; i < 5; i++) {
        ull wv[15];
        #pragma unroll
        for (int d = 0; d < 3; d++)
            #pragma unroll
            for (int j = 0; j < 5; j++)
                wv[d * 5 + j] = wps[d * 25 + i * 5 + j];

        const uint16_t* rowi = sp + ((r + i) * 16 + ZLO) * ICP + col0;

        #pragma unroll
        for (int kk = 0; kk < 9; kk++) {
            const u32* rk = reinterpret_cast<const u32*>(rowi + kk * ICP);
            uint2 ma = *reinterpret_cast<const uint2*>(rk);       // bf16 cols 0..3
            uint2 mb = *reinterpret_cast<const uint2*>(rk + 2);   // bf16 cols 4..7
            // bf16 -> fp32 (exact for 0.0 / 1.0)
            u32 v0 = ma.x << 16, v1 = ma.x & 0xFFFF0000u;
            u32 v2 = ma.y << 16, v3 = ma.y & 0xFFFF0000u;
            u32 v4 = mb.x << 16, v5 = mb.x & 0xFFFF0000u;
            u32 v6 = mb.y << 16, v7 = mb.y & 0xFFFF0000u;
            ull S[7];
            S[0] = pack2(v0, v1); S[1] = pack2(v1, v2);
            S[2] = pack2(v2, v3); S[3] = pack2(v3, v4);
            S[4] = pack2(v4, v5); S[5] = pack2(v5, v6);
            S[6] = pack2(v6, v7);

            #pragma unroll
            for (int d = 0; d < 3; d++) {
                const int zz = kk - d;              // compile-time per (kk,d)
                if (zz >= 0 && zz < 7) {
                    #pragma unroll
                    for (int j = 0; j < 5; j++) {
                        fma2(accA[zz], wv[d * 5 + j], S[j]);       // cols (c, c+1)
                        fma2(accB[zz], wv[d * 5 + j], S[j + 2]);   // cols (c+2, c+3)
                    }
                }
            }
        }
    }
}

template<int ZLO>
__device__ __forceinline__ void store_pass(float* __restrict__ out, int h, int w,
                                           float bv, const ull* accA, const ull* accB)
{
    if (h >= OH || w >= OW) return;
    const bool full = (w + 4 <= OW);
    #pragma unroll
    for (int zz = 0; zz < 7; zz++) {
        float2 a, b;
        a = *reinterpret_cast<const float2*>(&accA[zz]);
        b = *reinterpret_cast<const float2*>(&accB[zz]);
        size_t off = ((size_t)(ZLO + zz) * OH + h) * OW + w;
        if (full) {
            float4 v = make_float4(a.x + bv, a.y + bv, b.x + bv, b.y + bv);
            *reinterpret_cast<float4*>(out + off) = v;
        } else {
            float vals[4] = { a.x + bv, a.y + bv, b.x + bv, b.y + bv };
            #pragma unroll
            for (int c = 0; c < 4; c++)
                if (w + c < OW) out[off + c] = vals[c];
        }
    }
}

__global__ void __launch_bounds__(NTH, 3)
conv2dto3d_kernel(const int* __restrict__ x,
                  const float* __restrict__ weight,
                  const float* __restrict__ bias,
                  float* __restrict__ out)
{
    extern __shared__ unsigned char smem[];
    uint16_t* sp  = reinterpret_cast<uint16_t*>(smem);
    ull*      wps = reinterpret_cast<ull*>(smem + WOFF);

    const int tid   = threadIdx.x;
    const int wbase = blockIdx.x * TW;
    const int hbase = blockIdx.y * TH;

    if (tid < 75) {
        u32 wb = __float_as_uint(weight[tid]);
        wps[tid] = pack2(wb, wb);
    }

    // ---- expand tile to bf16 bit planes: sp[rr][k][cc] = bit k of pixel (exact) ----
    for (int pp = tid; pp < IR * (IC / 2); pp += NTH) {
        int rr = pp / (IC / 2);
        int c2 = (pp - rr * (IC / 2)) * 2;
        int ri = hbase + rr;  if (ri > IMG_N - 1) ri = IMG_N - 1;
        int c0 = wbase + c2;  if (c0 > IMG_N - 1) c0 = IMG_N - 1;
        int c1 = wbase + c2 + 1; if (c1 > IMG_N - 1) c1 = IMG_N - 1;
        u32 a0 = (u32)x[ri * IMG_N + c0];
        u32 a1 = (u32)x[ri * IMG_N + c1];
        #pragma unroll
        for (int k = 0; k < 16; k++) {
            u32 val = ((a0 >> k) & 1u) * 0x3F80u        // bf16(1.0) low half
                    | ((a1 >> k) & 1u) * 0x3F800000u;   // bf16(1.0) high half
            *reinterpret_cast<u32*>(sp + (rr * 16 + k) * ICP + c2) = val;
        }
    }
    __syncthreads();

    const int g = tid & 31;
    const int r = tid >> 5;
    const int col0 = g * 4;
    const int h = hbase + r;
    const int w = wbase + col0;
    const float bv = bias[0];

    ull accA[7], accB[7];

    run_pass<0>(sp, wps, r, col0, accA, accB);
    store_pass<0>(out, h, w, bv, accA, accB);

    run_pass<7>(sp, wps, r, col0, accA, accB);
    store_pass<7>(out, h, w, bv, accA, accB);
}

extern "C" void kernel_launch(void* const* d_in, const int* in_sizes, int n_in,
                              void* d_out, int out_size)
{
    const int*   x      = (const int*)d_in[0];
    const float* weight = (const float*)d_in[1];
    const float* bias   = (const float*)d_in[2];
    float*       out    = (float*)d_out;

    cudaFuncSetAttribute(conv2dto3d_kernel,
                         cudaFuncAttributeMaxDynamicSharedMemorySize, SMEM_BYTES);

    dim3 grid((OW + TW - 1) / TW, (OH + TH - 1) / TH);   // 16 x 256
    conv2dto3d_kernel<<<grid, NTH, SMEM_BYTES>>>(x, weight, bias, out);
}

// round 4
// speedup vs baseline: 1.2350x; 1.0042x over previous
#include <cuda_runtime.h>
#include <cstdint>

#define IMG_N  2048
#define OW     2044
#define OH     2044
#define TW     128
#define TH     8
#define IR     12          // TH + 4 input rows
#define IC     132         // TW + 4 input cols
#define ICP    136         // padded col stride (bf16 elements)
#define NTH    256

#define PLANES_U16 (IR * 16 * ICP)           // 26112 bf16
#define WOFF       (PLANES_U16 * 2)          // 52224 bytes
#define SMEM_BYTES (WOFF + 75 * 8)

typedef unsigned long long ull;
typedef unsigned int u32;

__device__ __forceinline__ void fma2(ull& acc, ull a, ull b) {
    asm("fma.rn.f32x2 %0, %1, %2, %0;" : "+l"(acc) : "l"(a), "l"(b));
}
__device__ __forceinline__ ull pack2(u32 lo, u32 hi) {
    ull r; asm("mov.b64 %0, {%1, %2};" : "=l"(r) : "r"(lo), "r"(hi)); return r;
}
// {f32(lo bf16 of u), f32(hi bf16 of u)} — 2 alu ops straight into an aligned pair
__device__ __forceinline__ ull mkpair_lohi(u32 u) {
    ull r;
    asm("{.reg .b32 a, b;\n\t"
        "shl.b32 a, %1, 16;\n\t"
        "and.b32 b, %1, 0xFFFF0000;\n\t"
        "mov.b64 %0, {a, b};}" : "=l"(r) : "r"(u));
    return r;
}
// {f32(hi bf16 of u), f32(lo bf16 of v)}
__device__ __forceinline__ ull mkpair_cross(u32 u, u32 v) {
    ull r;
    asm("{.reg .b32 a, b;\n\t"
        "and.b32 a, %1, 0xFFFF0000;\n\t"
        "shl.b32 b, %2, 16;\n\t"
        "mov.b64 %0, {a, b};}" : "=l"(r) : "r"(u), "r"(v));
    return r;
}

// One z-pass: outputs z in [ZLO, ZLO+6], consuming bit planes k in [ZLO, ZLO+8].
template<int ZLO>
__device__ __forceinline__ void run_pass(const uint16_t* __restrict__ sp,
                                         const ull* __restrict__ wps,
                                         int r, int col0, ull* accA, ull* accB)
{
    #pragma unroll
    for (int z = 0; z < 7; z++) { accA[z] = 0ull; accB[z] = 0ull; }

    #pragma unroll 1
    for (int i = 0; i < 5; i++) {
        ull wv[15];
        #pragma unroll
        for (int d = 0; d < 3; d++)
            #pragma unroll
            for (int j = 0; j < 5; j++)
                wv[d * 5 + j] = wps[d * 25 + i * 5 + j];

        const uint16_t* rowi = sp + ((r + i) * 16 + ZLO) * ICP + col0;

        #pragma unroll
        for (int kk = 0; kk < 9; kk++) {
            const u32* rk = reinterpret_cast<const u32*>(rowi + kk * ICP);
            uint2 ma = *reinterpret_cast<const uint2*>(rk);       // bf16 cols 0..3
            uint2 mb = *reinterpret_cast<const uint2*>(rk + 2);   // bf16 cols 4..7

            ull S[7];
            S[0] = mkpair_lohi (ma.x);          // (0,1)
            S[1] = mkpair_cross(ma.x, ma.y);    // (1,2)
            S[2] = mkpair_lohi (ma.y);          // (2,3)
            S[3] = mkpair_cross(ma.y, mb.x);    // (3,4)
            S[4] = mkpair_lohi (mb.x);          // (4,5)
            S[5] = mkpair_cross(mb.x, mb.y);    // (5,6)
            S[6] = mkpair_lohi (mb.y);          // (6,7)

            #pragma unroll
            for (int d = 0; d < 3; d++) {
                const int zz = kk - d;
                if (zz >= 0 && zz < 7) {
                    #pragma unroll
                    for (int j = 0; j < 5; j++) {
                        fma2(accA[zz], wv[d * 5 + j], S[j]);       // cols (c, c+1)
                        fma2(accB[zz], wv[d * 5 + j], S[j + 2]);   // cols (c+2, c+3)
                    }
                }
            }
        }
    }
}

template<int ZLO>
__device__ __forceinline__ void store_pass(float* __restrict__ out, int h, int w,
                                           float bv, const ull* accA, const ull* accB)
{
    if (h >= OH || w >= OW) return;
    const bool full = (w + 4 <= OW);
    #pragma unroll
    for (int zz = 0; zz < 7; zz++) {
        float2 a = *reinterpret_cast<const float2*>(&accA[zz]);
        float2 b = *reinterpret_cast<const float2*>(&accB[zz]);
        size_t off = ((size_t)(ZLO + zz) * OH + h) * OW + w;
        if (full) {
            float4 v = make_float4(a.x + bv, a.y + bv, b.x + bv, b.y + bv);
            *reinterpret_cast<float4*>(out + off) = v;
        } else {
            float vals[4] = { a.x + bv, a.y + bv, b.x + bv, b.y + bv };
            #pragma unroll
            for (int c = 0; c < 4; c++)
                if (w + c < OW) out[off + c] = vals[c];
        }
    }
}

__global__ void __launch_bounds__(NTH, 3)
conv2dto3d_kernel(const int* __restrict__ x,
                  const float* __restrict__ weight,
                  const float* __restrict__ bias,
                  float* __restrict__ out)
{
    extern __shared__ unsigned char smem[];
    uint16_t* sp  = reinterpret_cast<uint16_t*>(smem);
    ull*      wps = reinterpret_cast<ull*>(smem + WOFF);

    const int tid   = threadIdx.x;
    const int wbase = blockIdx.x * TW;
    const int hbase = blockIdx.y * TH;

    if (tid < 75) {
        u32 wb = __float_as_uint(weight[tid]);
        wps[tid] = pack2(wb, wb);
    }

    // ---- expand tile to bf16 bit planes: sp[rr][k][cc] = bit k of pixel (exact) ----
    for (int pp = tid; pp < IR * (IC / 2); pp += NTH) {
        int rr = pp / (IC / 2);
        int c2 = (pp - rr * (IC / 2)) * 2;
        int ri = hbase + rr;     if (ri > IMG_N - 1) ri = IMG_N - 1;
        int c0 = wbase + c2;     if (c0 > IMG_N - 1) c0 = IMG_N - 1;
        int c1 = wbase + c2 + 1; if (c1 > IMG_N - 1) c1 = IMG_N - 1;
        u32 a0 = (u32)x[ri * IMG_N + c0];
        u32 a1 = (u32)x[ri * IMG_N + c1];
        #pragma unroll
        for (int k = 0; k < 16; k++) {
            u32 val = ((a0 >> k) & 1u) * 0x3F80u
                    | ((a1 >> k) & 1u) * 0x3F800000u;
            *reinterpret_cast<u32*>(sp + (rr * 16 + k) * ICP + c2) = val;
        }
    }
    __syncthreads();

    const int g = tid & 31;
    const int r = tid >> 5;
    const int col0 = g * 4;
    const int h = hbase + r;
    const int w = wbase + col0;
    const float bv = bias[0];

    ull accA[7], accB[7];

    run_pass<0>(sp, wps, r, col0, accA, accB);
    store_pass<0>(out, h, w, bv, accA, accB);

    run_pass<7>(sp, wps, r, col0, accA, accB);
    store_pass<7>(out, h, w, bv, accA, accB);
}

extern "C" void kernel_launch(void* const* d_in, const int* in_sizes, int n_in,
                              void* d_out, int out_size)
{
    const int*   x      = (const int*)d_in[0];
    const float* weight = (const float*)d_in[1];
    const float* bias   = (const float*)d_in[2];
    float*       out    = (float*)d_out;

    cudaFuncSetAttribute(conv2dto3d_kernel,
                         cudaFuncAttributeMaxDynamicSharedMemorySize, SMEM_BYTES);

    dim3 grid((OW + TW - 1) / TW, (OH + TH - 1) / TH);   // 16 x 256
    conv2dto3d_kernel<<<grid, NTH, SMEM_BYTES>>>(x, weight, bias, out);
}